// round 1
// baseline (speedup 1.0000x reference)
#include <cuda_runtime.h>
#include <math.h>

#define BB   4
#define NN   2048
#define KCC  2048
#define DD   1024
#define HH   16
#define HD   64
#define SCALE_F 0.125f
#define EPS_F   1e-6f

// ---------------- scratch (static __device__, no allocation) ----------------
__device__ float g_ctxn[BB * KCC * DD];
__device__ float g_q   [BB * NN  * DD];
__device__ float g_k   [BB * KCC * DD];
__device__ float g_v   [BB * KCC * DD];
__device__ float g_ao  [BB * NN  * DD];

// ---------------- rms norm ----------------
__global__ void rmsnorm_k(const float* __restrict__ ctx, float* __restrict__ o) {
    int row = blockIdx.x;
    const float4* p = reinterpret_cast<const float4*>(ctx + (size_t)row * DD);
    float4 v = p[threadIdx.x];
    float ss = v.x * v.x + v.y * v.y + v.z * v.z + v.w * v.w;
    __shared__ float red[8];
    #pragma unroll
    for (int off = 16; off; off >>= 1) ss += __shfl_xor_sync(0xffffffffu, ss, off);
    if ((threadIdx.x & 31) == 0) red[threadIdx.x >> 5] = ss;
    __syncthreads();
    if (threadIdx.x < 32) {
        float t = (threadIdx.x < 8) ? red[threadIdx.x] : 0.0f;
        #pragma unroll
        for (int off = 4; off; off >>= 1) t += __shfl_xor_sync(0xffffffffu, t, off);
        if (threadIdx.x == 0) red[0] = t;
    }
    __syncthreads();
    float r = 1.0f / sqrtf(red[0] * (1.0f / DD) + EPS_F);
    float4* q = reinterpret_cast<float4*>(o + (size_t)row * DD);
    float4 w; w.x = v.x * r; w.y = v.y * r; w.z = v.z * r; w.w = v.w * r;
    q[threadIdx.x] = w;
}

// ---------------- SGEMM: C[M,N2] = A[M,K2] @ W[K2,N2] + bias ----------------
// MODE 0: scale by SCALE_F, write C         (q projection)
// MODE 1: split cols: <D -> outK, >=D -> outV (kv projection)
// MODE 2: plain write C                     (output projection)
#define BM 128
#define BN 128
#define BKk 8
#define AP 132   // padded pitch for As (conflict-free transposed store)

template <int MODE>
__global__ void __launch_bounds__(256, 2)
sgemm_k(const float* __restrict__ A, const float* __restrict__ W,
        const float* __restrict__ bias, float* __restrict__ C,
        int M2, int N2, int K2,
        float* __restrict__ outK, float* __restrict__ outV) {
    __shared__ float As[2][BKk * AP];
    __shared__ float Bs[2][BKk * BN];

    int tid = threadIdx.x;
    int tx = tid & 15;
    int ty = tid >> 4;
    int rowBase = blockIdx.y * BM;
    int colBase = blockIdx.x * BN;

    int arow = tid >> 1;          // 0..127
    int acol = (tid & 1) << 2;    // 0 or 4
    int brow = tid >> 5;          // 0..7
    int bcol = (tid & 31) << 2;   // 0..124

    const float* Aptr = A + (size_t)(rowBase + arow) * K2 + acol;
    const float* Bptr = W + (size_t)brow * N2 + colBase + bcol;

    float4 a4 = *reinterpret_cast<const float4*>(Aptr);
    float4 b4 = *reinterpret_cast<const float4*>(Bptr);
    As[0][(acol + 0) * AP + arow] = a4.x;
    As[0][(acol + 1) * AP + arow] = a4.y;
    As[0][(acol + 2) * AP + arow] = a4.z;
    As[0][(acol + 3) * AP + arow] = a4.w;
    *reinterpret_cast<float4*>(&Bs[0][brow * BN + bcol]) = b4;
    __syncthreads();

    float acc[8][8];
    #pragma unroll
    for (int i = 0; i < 8; ++i)
        #pragma unroll
        for (int j = 0; j < 8; ++j) acc[i][j] = 0.0f;

    int nT = K2 / BKk;
    int cur = 0;
    for (int t = 0; t < nT; ++t) {
        if (t + 1 < nT) {
            a4 = *reinterpret_cast<const float4*>(Aptr + (t + 1) * BKk);
            b4 = *reinterpret_cast<const float4*>(Bptr + (size_t)(t + 1) * BKk * N2);
        }
        #pragma unroll
        for (int k = 0; k < BKk; ++k) {
            float4 a0 = *reinterpret_cast<float4*>(&As[cur][k * AP + ty * 8]);
            float4 a1 = *reinterpret_cast<float4*>(&As[cur][k * AP + ty * 8 + 4]);
            float4 b0 = *reinterpret_cast<float4*>(&Bs[cur][k * BN + tx * 8]);
            float4 b1 = *reinterpret_cast<float4*>(&Bs[cur][k * BN + tx * 8 + 4]);
            float ra[8] = {a0.x, a0.y, a0.z, a0.w, a1.x, a1.y, a1.z, a1.w};
            float rb[8] = {b0.x, b0.y, b0.z, b0.w, b1.x, b1.y, b1.z, b1.w};
            #pragma unroll
            for (int i = 0; i < 8; ++i)
                #pragma unroll
                for (int j = 0; j < 8; ++j)
                    acc[i][j] += ra[i] * rb[j];
        }
        if (t + 1 < nT) {
            int nxt = cur ^ 1;
            As[nxt][(acol + 0) * AP + arow] = a4.x;
            As[nxt][(acol + 1) * AP + arow] = a4.y;
            As[nxt][(acol + 2) * AP + arow] = a4.z;
            As[nxt][(acol + 3) * AP + arow] = a4.w;
            *reinterpret_cast<float4*>(&Bs[nxt][brow * BN + bcol]) = b4;
        }
        __syncthreads();
        cur ^= 1;
    }

    int row0 = rowBase + ty * 8;
    int col0 = colBase + tx * 8;
    #pragma unroll
    for (int i = 0; i < 8; ++i) {
        int row = row0 + i;
        #pragma unroll
        for (int j0 = 0; j0 < 8; j0 += 4) {
            float4 r;
            r.x = acc[i][j0 + 0] + bias[col0 + j0 + 0];
            r.y = acc[i][j0 + 1] + bias[col0 + j0 + 1];
            r.z = acc[i][j0 + 2] + bias[col0 + j0 + 2];
            r.w = acc[i][j0 + 3] + bias[col0 + j0 + 3];
            if (MODE == 0) {
                r.x *= SCALE_F; r.y *= SCALE_F; r.z *= SCALE_F; r.w *= SCALE_F;
                *reinterpret_cast<float4*>(&C[(size_t)row * N2 + col0 + j0]) = r;
            } else if (MODE == 2) {
                *reinterpret_cast<float4*>(&C[(size_t)row * N2 + col0 + j0]) = r;
            } else {
                int cg = col0 + j0;
                if (cg < DD)
                    *reinterpret_cast<float4*>(&outK[(size_t)row * DD + cg]) = r;
                else
                    *reinterpret_cast<float4*>(&outV[(size_t)row * DD + cg - DD]) = r;
            }
        }
    }
}

// ---------------- fused attention ----------------
// grid: (NN/128, BB*HH), 256 threads. Per block: 128 q-rows for one (b,h).
// clip(-10,10) => row max <= 10 => p = exp(s-10), no running-max rescale.
#define QP 132   // Qt/Pt pitch (128 rows + pad)
#define KP 68    // Kt/Vs pitch (64 cols + pad)
#define ATTN_SMEM ((64 * QP + 64 * KP + 64 * KP + 64 * QP) * 4)

__global__ void __launch_bounds__(256, 2)
attn_k(const float* __restrict__ q, const float* __restrict__ kk,
       const float* __restrict__ vv, float* __restrict__ o) {
    extern __shared__ float sm[];
    float* Qt = sm;                      // [64][QP] : Qt[d][n]
    float* Kt = Qt + 64 * QP;            // [64][KP] : Kt[d][c]
    float* Vs = Kt + 64 * KP;            // [64][KP] : Vs[c][dv]
    float* Pt = Vs + 64 * KP;            // [64][QP] : Pt[c][n]

    int tid = threadIdx.x;
    int tx = tid & 15;
    int ty = tid >> 4;
    int bh = blockIdx.y;
    int b = bh >> 4;
    int h = bh & 15;
    int n0 = blockIdx.x * 128;

    const float* qbase = q + ((size_t)(b * NN + n0)) * DD + h * HD;
    #pragma unroll
    for (int it = 0; it < 8; ++it) {
        int idx = tid + 256 * it;
        int n = idx >> 4;
        int dq = (idx & 15) << 2;
        float4 t = *reinterpret_cast<const float4*>(qbase + (size_t)n * DD + dq);
        Qt[(dq + 0) * QP + n] = t.x;
        Qt[(dq + 1) * QP + n] = t.y;
        Qt[(dq + 2) * QP + n] = t.z;
        Qt[(dq + 3) * QP + n] = t.w;
    }

    float acc[8][4];
    float rs[8];
    #pragma unroll
    for (int i = 0; i < 8; ++i) {
        rs[i] = 0.0f;
        #pragma unroll
        for (int j = 0; j < 4; ++j) acc[i][j] = 0.0f;
    }

    const float* kbase = kk + (size_t)b * KCC * DD + h * HD;
    const float* vbase = vv + (size_t)b * KCC * DD + h * HD;

    for (int kc0 = 0; kc0 < KCC; kc0 += 64) {
        __syncthreads();  // also orders Q stores before first read; guards Kt/Vs/Pt reuse
        #pragma unroll
        for (int it = 0; it < 4; ++it) {
            int idx = tid + 256 * it;
            int c = idx >> 4;
            int dq = (idx & 15) << 2;
            float4 t = *reinterpret_cast<const float4*>(kbase + (size_t)(kc0 + c) * DD + dq);
            Kt[(dq + 0) * KP + c] = t.x;
            Kt[(dq + 1) * KP + c] = t.y;
            Kt[(dq + 2) * KP + c] = t.z;
            Kt[(dq + 3) * KP + c] = t.w;
            float4 u = *reinterpret_cast<const float4*>(vbase + (size_t)(kc0 + c) * DD + dq);
            *reinterpret_cast<float4*>(&Vs[c * KP + dq]) = u;
        }
        __syncthreads();

        float s[8][4];
        #pragma unroll
        for (int i = 0; i < 8; ++i)
            #pragma unroll
            for (int j = 0; j < 4; ++j) s[i][j] = 0.0f;

        #pragma unroll 8
        for (int d = 0; d < 64; ++d) {
            float4 q0 = *reinterpret_cast<float4*>(&Qt[d * QP + ty * 8]);
            float4 q1 = *reinterpret_cast<float4*>(&Qt[d * QP + ty * 8 + 4]);
            float4 kf = *reinterpret_cast<float4*>(&Kt[d * KP + tx * 4]);
            float ra[8] = {q0.x, q0.y, q0.z, q0.w, q1.x, q1.y, q1.z, q1.w};
            float rb[4] = {kf.x, kf.y, kf.z, kf.w};
            #pragma unroll
            for (int i = 0; i < 8; ++i)
                #pragma unroll
                for (int j = 0; j < 4; ++j)
                    s[i][j] += ra[i] * rb[j];
        }

        #pragma unroll
        for (int i = 0; i < 8; ++i)
            #pragma unroll
            for (int j = 0; j < 4; ++j) {
                float sv = fminf(fmaxf(s[i][j], -10.0f), 10.0f);
                float p = __expf(sv - 10.0f);
                rs[i] += p;
                Pt[(tx * 4 + j) * QP + ty * 8 + i] = p;
            }
        __syncthreads();

        #pragma unroll 8
        for (int c = 0; c < 64; ++c) {
            float4 p0 = *reinterpret_cast<float4*>(&Pt[c * QP + ty * 8]);
            float4 p1 = *reinterpret_cast<float4*>(&Pt[c * QP + ty * 8 + 4]);
            float4 vf = *reinterpret_cast<float4*>(&Vs[c * KP + tx * 4]);
            float rp[8] = {p0.x, p0.y, p0.z, p0.w, p1.x, p1.y, p1.z, p1.w};
            float rv[4] = {vf.x, vf.y, vf.z, vf.w};
            #pragma unroll
            for (int i = 0; i < 8; ++i)
                #pragma unroll
                for (int j = 0; j < 4; ++j)
                    acc[i][j] += rp[i] * rv[j];
        }
    }

    // reduce row sums across the 16 threads (same ty) that share each row group
    #pragma unroll
    for (int i = 0; i < 8; ++i) {
        float t = rs[i];
        #pragma unroll
        for (int off = 8; off; off >>= 1)
            t += __shfl_xor_sync(0xffffffffu, t, off, 16);
        rs[i] = t;
    }

    #pragma unroll
    for (int i = 0; i < 8; ++i) {
        float inv = 1.0f / rs[i];
        int n = n0 + ty * 8 + i;
        float4 r;
        r.x = acc[i][0] * inv;
        r.y = acc[i][1] * inv;
        r.z = acc[i][2] * inv;
        r.w = acc[i][3] * inv;
        *reinterpret_cast<float4*>(&o[((size_t)(b * NN + n)) * DD + h * HD + tx * 4]) = r;
    }
}

// ---------------- tail: attn.mean() == 1/KC (softmax rows sum to 1) ----------
__global__ void tail_k(float* __restrict__ dst) {
    dst[0] = 1.0f / (float)KCC;
}

// ---------------- launch ----------------
extern "C" void kernel_launch(void* const* d_in, const int* in_sizes, int n_in,
                              void* d_out, int out_size) {
    const float* x      = (const float*)d_in[0];
    const float* ctx    = (const float*)d_in[1];
    const float* q_w    = (const float*)d_in[2];
    const float* q_b    = (const float*)d_in[3];
    const float* kv_w   = (const float*)d_in[4];
    const float* kv_b   = (const float*)d_in[5];
    const float* proj_w = (const float*)d_in[6];
    const float* proj_b = (const float*)d_in[7];
    float* out = (float*)d_out;

    float *ctxn, *qg, *kg, *vg, *ao;
    cudaGetSymbolAddress((void**)&ctxn, g_ctxn);
    cudaGetSymbolAddress((void**)&qg,   g_q);
    cudaGetSymbolAddress((void**)&kg,   g_k);
    cudaGetSymbolAddress((void**)&vg,   g_v);
    cudaGetSymbolAddress((void**)&ao,   g_ao);

    cudaFuncSetAttribute(attn_k, cudaFuncAttributeMaxDynamicSharedMemorySize, ATTN_SMEM);

    rmsnorm_k<<<BB * KCC, 256>>>(ctx, ctxn);

    dim3 gq(DD / BN, (BB * NN) / BM);
    sgemm_k<0><<<gq, 256>>>(x, q_w, q_b, qg, BB * NN, DD, DD, nullptr, nullptr);

    dim3 gkv((2 * DD) / BN, (BB * KCC) / BM);
    sgemm_k<1><<<gkv, 256>>>(ctxn, kv_w, kv_b, nullptr, BB * KCC, 2 * DD, DD, kg, vg);

    dim3 ga(NN / 128, BB * HH);
    attn_k<<<ga, 256, ATTN_SMEM>>>(qg, kg, vg, ao);

    dim3 gp(DD / BN, (BB * NN) / BM);
    sgemm_k<2><<<gp, 256>>>(ao, proj_w, proj_b, out, BB * NN, DD, DD, nullptr, nullptr);

    if (out_size > BB * NN * DD) {
        tail_k<<<1, 1>>>(out + (size_t)BB * NN * DD);
    }
}

// round 2
// speedup vs baseline: 2.7537x; 2.7537x over previous
#include <cuda_runtime.h>
#include <math.h>
#include <stdint.h>

#define BB   4
#define NN   2048
#define KCC  2048
#define DD   1024
#define HH   16
#define HD   64
#define SCALE_F 0.125f
#define EPS_F   1e-6f

// ---------------- scratch ----------------
__device__ float g_ctxn[BB * KCC * DD];
__device__ float g_q   [BB * NN  * DD];
__device__ float g_k   [BB * KCC * DD];
__device__ float g_v   [BB * KCC * DD];
__device__ float g_ao  [BB * NN  * DD];

// ---------------- tf32 helpers ----------------
__device__ __forceinline__ uint32_t f2tf(float f) {
    uint32_t u;
    asm("cvt.rna.tf32.f32 %0, %1;" : "=r"(u) : "f"(f));
    return u;
}
__device__ __forceinline__ void mma8(float* c, const uint32_t* a, const uint32_t* b) {
    asm volatile(
        "mma.sync.aligned.m16n8k8.row.col.f32.tf32.tf32.f32 "
        "{%0,%1,%2,%3}, {%4,%5,%6,%7}, {%8,%9}, {%0,%1,%2,%3};"
        : "+f"(c[0]), "+f"(c[1]), "+f"(c[2]), "+f"(c[3])
        : "r"(a[0]), "r"(a[1]), "r"(a[2]), "r"(a[3]), "r"(b[0]), "r"(b[1]));
}

// ---------------- rms norm ----------------
__global__ void rmsnorm_k(const float* __restrict__ ctx, float* __restrict__ o) {
    int row = blockIdx.x;
    const float4* p = reinterpret_cast<const float4*>(ctx + (size_t)row * DD);
    float4 v = p[threadIdx.x];
    float ss = v.x * v.x + v.y * v.y + v.z * v.z + v.w * v.w;
    __shared__ float red[8];
    #pragma unroll
    for (int off = 16; off; off >>= 1) ss += __shfl_xor_sync(0xffffffffu, ss, off);
    if ((threadIdx.x & 31) == 0) red[threadIdx.x >> 5] = ss;
    __syncthreads();
    if (threadIdx.x < 32) {
        float t = (threadIdx.x < 8) ? red[threadIdx.x] : 0.0f;
        #pragma unroll
        for (int off = 4; off; off >>= 1) t += __shfl_xor_sync(0xffffffffu, t, off);
        if (threadIdx.x == 0) red[0] = t;
    }
    __syncthreads();
    float r = 1.0f / sqrtf(red[0] * (1.0f / DD) + EPS_F);
    float4* q = reinterpret_cast<float4*>(o + (size_t)row * DD);
    float4 w; w.x = v.x * r; w.y = v.y * r; w.z = v.z * r; w.w = v.w * r;
    q[threadIdx.x] = w;
}

// ---------------- tf32 tensor-core GEMM ----------------
// C[M,N2] = A[M,K2] @ W[K2,N2] + bias.   Block 128x256, BK=32, 8 warps @64x64.
#define GAP 36
#define GBP 264
#define GASZ (128 * GAP)
#define GBSZ (32 * GBP)
#define GEMM_SMEM ((2 * GASZ + 2 * GBSZ) * 4)

template <int MODE>
__global__ void __launch_bounds__(256)
gemm_tc(const float* __restrict__ A, const float* __restrict__ W,
        const float* __restrict__ bias, float* __restrict__ C,
        int M2, int N2, int K2,
        float* __restrict__ outK, float* __restrict__ outV) {
    extern __shared__ uint32_t smu[];
    uint32_t* As = smu;
    uint32_t* Bs = smu + 2 * GASZ;

    int tid = threadIdx.x;
    int lane = tid & 31;
    int wid = tid >> 5;
    int gid = lane >> 2, tig = lane & 3;
    int warpm = wid & 1, warpn = wid >> 1;
    int rowBase = blockIdx.y * 128, colBase = blockIdx.x * 256;

    int am = tid >> 3, ak = (tid & 7) << 2;
    int bn = (tid & 63) << 2, bk = tid >> 6;

    const float* Ap = A + (size_t)rowBase * K2;
    const float* Wp = W + colBase + bn;

    float4 ar[4], br[8];
    #pragma unroll
    for (int i = 0; i < 4; ++i)
        ar[i] = *(const float4*)(Ap + (size_t)(am + 32 * i) * K2 + ak);
    #pragma unroll
    for (int i = 0; i < 8; ++i)
        br[i] = *(const float4*)(Wp + (size_t)(bk + 4 * i) * N2);

    #pragma unroll
    for (int i = 0; i < 4; ++i) {
        uint32_t* p = &As[(am + 32 * i) * GAP + ak];
        p[0] = f2tf(ar[i].x); p[1] = f2tf(ar[i].y);
        p[2] = f2tf(ar[i].z); p[3] = f2tf(ar[i].w);
    }
    #pragma unroll
    for (int i = 0; i < 8; ++i) {
        uint32_t* p = &Bs[(bk + 4 * i) * GBP + bn];
        p[0] = f2tf(br[i].x); p[1] = f2tf(br[i].y);
        p[2] = f2tf(br[i].z); p[3] = f2tf(br[i].w);
    }
    __syncthreads();

    float acc[4][8][4];
    #pragma unroll
    for (int mt = 0; mt < 4; ++mt)
        #pragma unroll
        for (int nt = 0; nt < 8; ++nt)
            #pragma unroll
            for (int r = 0; r < 4; ++r) acc[mt][nt][r] = 0.0f;

    int nT = K2 >> 5;
    int cur = 0;
    for (int t = 0; t < nT; ++t) {
        if (t + 1 < nT) {
            const float* Ap2 = Ap + (t + 1) * 32;
            #pragma unroll
            for (int i = 0; i < 4; ++i)
                ar[i] = *(const float4*)(Ap2 + (size_t)(am + 32 * i) * K2 + ak);
            const float* Wp2 = Wp + (size_t)(t + 1) * 32 * N2;
            #pragma unroll
            for (int i = 0; i < 8; ++i)
                br[i] = *(const float4*)(Wp2 + (size_t)(bk + 4 * i) * N2);
        }
        const uint32_t* Ab = &As[cur * GASZ];
        const uint32_t* Bb = &Bs[cur * GBSZ];
        #pragma unroll
        for (int ks = 0; ks < 4; ++ks) {
            int tk = ks << 3;
            uint32_t af[4][4], bf[8][2];
            #pragma unroll
            for (int mt = 0; mt < 4; ++mt) {
                int m0 = warpm * 64 + mt * 16 + gid;
                af[mt][0] = Ab[m0 * GAP + tk + tig];
                af[mt][1] = Ab[(m0 + 8) * GAP + tk + tig];
                af[mt][2] = Ab[m0 * GAP + tk + tig + 4];
                af[mt][3] = Ab[(m0 + 8) * GAP + tk + tig + 4];
            }
            #pragma unroll
            for (int nt = 0; nt < 8; ++nt) {
                int n0 = warpn * 64 + nt * 8 + gid;
                bf[nt][0] = Bb[(tk + tig) * GBP + n0];
                bf[nt][1] = Bb[(tk + tig + 4) * GBP + n0];
            }
            #pragma unroll
            for (int mt = 0; mt < 4; ++mt)
                #pragma unroll
                for (int nt = 0; nt < 8; ++nt)
                    mma8(acc[mt][nt], af[mt], bf[nt]);
        }
        if (t + 1 < nT) {
            int nb = cur ^ 1;
            #pragma unroll
            for (int i = 0; i < 4; ++i) {
                uint32_t* p = &As[nb * GASZ + (am + 32 * i) * GAP + ak];
                p[0] = f2tf(ar[i].x); p[1] = f2tf(ar[i].y);
                p[2] = f2tf(ar[i].z); p[3] = f2tf(ar[i].w);
            }
            #pragma unroll
            for (int i = 0; i < 8; ++i) {
                uint32_t* p = &Bs[nb * GBSZ + (bk + 4 * i) * GBP + bn];
                p[0] = f2tf(br[i].x); p[1] = f2tf(br[i].y);
                p[2] = f2tf(br[i].z); p[3] = f2tf(br[i].w);
            }
        }
        __syncthreads();
        cur ^= 1;
    }

    #pragma unroll
    for (int mt = 0; mt < 4; ++mt) {
        int r0 = rowBase + warpm * 64 + mt * 16 + gid;
        #pragma unroll
        for (int nt = 0; nt < 8; ++nt) {
            int col = colBase + warpn * 64 + nt * 8 + tig * 2;
            float2 bb = *(const float2*)(bias + col);
            float2 v0, v1;
            v0.x = acc[mt][nt][0] + bb.x; v0.y = acc[mt][nt][1] + bb.y;
            v1.x = acc[mt][nt][2] + bb.x; v1.y = acc[mt][nt][3] + bb.y;
            if (MODE == 0) {
                v0.x *= SCALE_F; v0.y *= SCALE_F; v1.x *= SCALE_F; v1.y *= SCALE_F;
                *(float2*)(&C[(size_t)r0 * N2 + col]) = v0;
                *(float2*)(&C[(size_t)(r0 + 8) * N2 + col]) = v1;
            } else if (MODE == 2) {
                *(float2*)(&C[(size_t)r0 * N2 + col]) = v0;
                *(float2*)(&C[(size_t)(r0 + 8) * N2 + col]) = v1;
            } else {
                if (col < DD) {
                    *(float2*)(&outK[(size_t)r0 * DD + col]) = v0;
                    *(float2*)(&outK[(size_t)(r0 + 8) * DD + col]) = v1;
                } else {
                    *(float2*)(&outV[(size_t)r0 * DD + col - DD]) = v0;
                    *(float2*)(&outV[(size_t)(r0 + 8) * DD + col - DD]) = v1;
                }
            }
        }
    }
}

// ---------------- fused attention (tf32 mma) ----------------
#define QSP 68
#define PSP 132
#define QS_OFF 0
#define KS_OFF (128 * QSP)
#define VS_OFF (2 * 128 * QSP)
#define PS_OFF (3 * 128 * QSP)
#define RS_OFF (3 * 128 * QSP + 128 * PSP)
#define ATTN_SMEM ((3 * 128 * QSP + 128 * PSP + 128) * 4)

__global__ void __launch_bounds__(256)
attn_k(const float* __restrict__ q, const float* __restrict__ kk,
       const float* __restrict__ vv, float* __restrict__ o) {
    extern __shared__ uint32_t smu[];
    uint32_t* Qs = smu + QS_OFF;
    uint32_t* Ks = smu + KS_OFF;
    uint32_t* Vs = smu + VS_OFF;
    uint32_t* Ps = smu + PS_OFF;
    float*    RS = (float*)(smu + RS_OFF);

    int tid = threadIdx.x;
    int lane = tid & 31;
    int wid = tid >> 5;
    int gid = lane >> 2, tig = lane & 3;
    int warpm = wid & 1, warpn = wid >> 1;      // S: 2m x 4n (64 x 32)
    int warpm2 = wid & 3, warpn2 = wid >> 2;    // PV: 4m x 2n (32 x 32)

    int bh = blockIdx.y;
    int b = bh >> 4;
    int h = bh & 15;
    int n0blk = blockIdx.x * 128;

    const float* qbase = q + ((size_t)(b * NN + n0blk)) * DD + h * HD;
    const float* kbase = kk + (size_t)b * KCC * DD + h * HD;
    const float* vbase = vv + (size_t)b * KCC * DD + h * HD;

    #pragma unroll
    for (int i = 0; i < 8; ++i) {
        int idx = tid + 256 * i;
        int row = idx >> 4;
        int d4 = (idx & 15) << 2;
        float4 t = *(const float4*)(qbase + (size_t)row * DD + d4);
        uint32_t* p = &Qs[row * QSP + d4];
        p[0] = f2tf(t.x); p[1] = f2tf(t.y); p[2] = f2tf(t.z); p[3] = f2tf(t.w);
    }
    if (tid < 128) RS[tid] = 0.0f;

    float oAcc[2][4][4];
    #pragma unroll
    for (int mt = 0; mt < 2; ++mt)
        #pragma unroll
        for (int nt = 0; nt < 4; ++nt)
            #pragma unroll
            for (int r = 0; r < 4; ++r) oAcc[mt][nt][r] = 0.0f;
    float rs[8];
    #pragma unroll
    for (int i = 0; i < 8; ++i) rs[i] = 0.0f;

    for (int kc0 = 0; kc0 < KCC; kc0 += 128) {
        float4 kr[8], vr[8];
        #pragma unroll
        for (int i = 0; i < 8; ++i) {
            int idx = tid + 256 * i;
            int key = idx >> 4;
            int d4 = (idx & 15) << 2;
            kr[i] = *(const float4*)(kbase + (size_t)(kc0 + key) * DD + d4);
            vr[i] = *(const float4*)(vbase + (size_t)(kc0 + key) * DD + d4);
        }
        __syncthreads();
        #pragma unroll
        for (int i = 0; i < 8; ++i) {
            int idx = tid + 256 * i;
            int key = idx >> 4;
            int d4 = (idx & 15) << 2;
            uint32_t* pk = &Ks[key * QSP + d4];
            pk[0] = f2tf(kr[i].x); pk[1] = f2tf(kr[i].y);
            pk[2] = f2tf(kr[i].z); pk[3] = f2tf(kr[i].w);
            uint32_t* pv = &Vs[key * QSP + d4];
            pv[0] = f2tf(vr[i].x); pv[1] = f2tf(vr[i].y);
            pv[2] = f2tf(vr[i].z); pv[3] = f2tf(vr[i].w);
        }
        __syncthreads();

        float sAcc[4][4][4];
        #pragma unroll
        for (int mt = 0; mt < 4; ++mt)
            #pragma unroll
            for (int nt = 0; nt < 4; ++nt)
                #pragma unroll
                for (int r = 0; r < 4; ++r) sAcc[mt][nt][r] = 0.0f;

        #pragma unroll
        for (int ks = 0; ks < 8; ++ks) {
            int tk = ks << 3;
            uint32_t af[4][4], bf[4][2];
            #pragma unroll
            for (int mt = 0; mt < 4; ++mt) {
                int m0 = warpm * 64 + mt * 16 + gid;
                af[mt][0] = Qs[m0 * QSP + tk + tig];
                af[mt][1] = Qs[(m0 + 8) * QSP + tk + tig];
                af[mt][2] = Qs[m0 * QSP + tk + tig + 4];
                af[mt][3] = Qs[(m0 + 8) * QSP + tk + tig + 4];
            }
            #pragma unroll
            for (int nt = 0; nt < 4; ++nt) {
                int n0 = warpn * 32 + nt * 8 + gid;
                bf[nt][0] = Ks[n0 * QSP + tk + tig];
                bf[nt][1] = Ks[n0 * QSP + tk + tig + 4];
            }
            #pragma unroll
            for (int mt = 0; mt < 4; ++mt)
                #pragma unroll
                for (int nt = 0; nt < 4; ++nt)
                    mma8(sAcc[mt][nt], af[mt], bf[nt]);
        }

        #pragma unroll
        for (int mt = 0; mt < 4; ++mt) {
            int r0 = warpm * 64 + mt * 16 + gid;
            #pragma unroll
            for (int nt = 0; nt < 4; ++nt) {
                int col = warpn * 32 + nt * 8 + tig * 2;
                float p0 = __expf(fminf(fmaxf(sAcc[mt][nt][0], -10.0f), 10.0f) - 10.0f);
                float p1 = __expf(fminf(fmaxf(sAcc[mt][nt][1], -10.0f), 10.0f) - 10.0f);
                float p2 = __expf(fminf(fmaxf(sAcc[mt][nt][2], -10.0f), 10.0f) - 10.0f);
                float p3 = __expf(fminf(fmaxf(sAcc[mt][nt][3], -10.0f), 10.0f) - 10.0f);
                uint32_t u0 = f2tf(p0), u1 = f2tf(p1), u2 = f2tf(p2), u3 = f2tf(p3);
                rs[mt * 2 + 0] += __uint_as_float(u0) + __uint_as_float(u1);
                rs[mt * 2 + 1] += __uint_as_float(u2) + __uint_as_float(u3);
                uint2 w0; w0.x = u0; w0.y = u1;
                uint2 w1; w1.x = u2; w1.y = u3;
                *(uint2*)(&Ps[r0 * PSP + col]) = w0;
                *(uint2*)(&Ps[(r0 + 8) * PSP + col]) = w1;
            }
        }
        __syncthreads();

        #pragma unroll
        for (int ks = 0; ks < 16; ++ks) {
            int tk = ks << 3;
            uint32_t af[2][4], bf[4][2];
            #pragma unroll
            for (int mt = 0; mt < 2; ++mt) {
                int m0 = warpm2 * 32 + mt * 16 + gid;
                af[mt][0] = Ps[m0 * PSP + tk + tig];
                af[mt][1] = Ps[(m0 + 8) * PSP + tk + tig];
                af[mt][2] = Ps[m0 * PSP + tk + tig + 4];
                af[mt][3] = Ps[(m0 + 8) * PSP + tk + tig + 4];
            }
            #pragma unroll
            for (int nt = 0; nt < 4; ++nt) {
                int n0 = warpn2 * 32 + nt * 8 + gid;
                bf[nt][0] = Vs[(tk + tig) * QSP + n0];
                bf[nt][1] = Vs[(tk + tig + 4) * QSP + n0];
            }
            #pragma unroll
            for (int mt = 0; mt < 2; ++mt)
                #pragma unroll
                for (int nt = 0; nt < 4; ++nt)
                    mma8(oAcc[mt][nt], af[mt], bf[nt]);
        }
    }

    #pragma unroll
    for (int mt = 0; mt < 4; ++mt)
        #pragma unroll
        for (int rr = 0; rr < 2; ++rr) {
            float v = rs[mt * 2 + rr];
            v += __shfl_xor_sync(0xffffffffu, v, 1);
            v += __shfl_xor_sync(0xffffffffu, v, 2);
            if (tig == 0)
                atomicAdd(&RS[warpm * 64 + mt * 16 + rr * 8 + gid], v);
        }
    __syncthreads();

    #pragma unroll
    for (int mt = 0; mt < 2; ++mt) {
        int r0 = warpm2 * 32 + mt * 16 + gid;
        float inv0 = 1.0f / RS[r0];
        float inv1 = 1.0f / RS[r0 + 8];
        #pragma unroll
        for (int nt = 0; nt < 4; ++nt) {
            int dv = warpn2 * 32 + nt * 8 + tig * 2;
            float2 w0, w1;
            w0.x = oAcc[mt][nt][0] * inv0; w0.y = oAcc[mt][nt][1] * inv0;
            w1.x = oAcc[mt][nt][2] * inv1; w1.y = oAcc[mt][nt][3] * inv1;
            *(float2*)(&o[((size_t)(b * NN + n0blk + r0)) * DD + h * HD + dv]) = w0;
            *(float2*)(&o[((size_t)(b * NN + n0blk + r0 + 8)) * DD + h * HD + dv]) = w1;
        }
    }
}

// ---------------- tail ----------------
__global__ void tail_k(float* __restrict__ dst) {
    dst[0] = 1.0f / (float)KCC;
}

// ---------------- launch ----------------
extern "C" void kernel_launch(void* const* d_in, const int* in_sizes, int n_in,
                              void* d_out, int out_size) {
    const float* x      = (const float*)d_in[0];
    const float* ctx    = (const float*)d_in[1];
    const float* q_w    = (const float*)d_in[2];
    const float* q_b    = (const float*)d_in[3];
    const float* kv_w   = (const float*)d_in[4];
    const float* kv_b   = (const float*)d_in[5];
    const float* proj_w = (const float*)d_in[6];
    const float* proj_b = (const float*)d_in[7];
    float* out = (float*)d_out;

    float *ctxn, *qg, *kg, *vg, *ao;
    cudaGetSymbolAddress((void**)&ctxn, g_ctxn);
    cudaGetSymbolAddress((void**)&qg,   g_q);
    cudaGetSymbolAddress((void**)&kg,   g_k);
    cudaGetSymbolAddress((void**)&vg,   g_v);
    cudaGetSymbolAddress((void**)&ao,   g_ao);

    cudaFuncSetAttribute(gemm_tc<0>, cudaFuncAttributeMaxDynamicSharedMemorySize, GEMM_SMEM);
    cudaFuncSetAttribute(gemm_tc<1>, cudaFuncAttributeMaxDynamicSharedMemorySize, GEMM_SMEM);
    cudaFuncSetAttribute(gemm_tc<2>, cudaFuncAttributeMaxDynamicSharedMemorySize, GEMM_SMEM);
    cudaFuncSetAttribute(attn_k,     cudaFuncAttributeMaxDynamicSharedMemorySize, ATTN_SMEM);

    rmsnorm_k<<<BB * KCC, 256>>>(ctx, ctxn);

    dim3 gq(DD / 256, (BB * NN) / 128);
    gemm_tc<0><<<gq, 256, GEMM_SMEM>>>(x, q_w, q_b, qg, BB * NN, DD, DD, nullptr, nullptr);

    dim3 gkv((2 * DD) / 256, (BB * KCC) / 128);
    gemm_tc<1><<<gkv, 256, GEMM_SMEM>>>(ctxn, kv_w, kv_b, nullptr, BB * KCC, 2 * DD, DD, kg, vg);

    dim3 ga(NN / 128, BB * HH);
    attn_k<<<ga, 256, ATTN_SMEM>>>(qg, kg, vg, ao);

    dim3 gp(DD / 256, (BB * NN) / 128);
    gemm_tc<2><<<gp, 256, GEMM_SMEM>>>(ao, proj_w, proj_b, out, BB * NN, DD, DD, nullptr, nullptr);

    if (out_size > BB * NN * DD) {
        tail_k<<<1, 1>>>(out + (size_t)BB * NN * DD);
    }
}